// round 9
// baseline (speedup 1.0000x reference)
#include <cuda_runtime.h>

#define NB 256
#define NS 1024
#define ND 512
#define CHUNK_S 128
#define CHUNKS_PER_B (NS / CHUNK_S)          // 8
#define NUNITS (NB * CHUNKS_PER_B)           // 2048
#define NCTA 296                             // 2 per SM on 148 SMs

__device__ float    g_acc[NB * ND];
__device__ float    g_l[NB];
__device__ unsigned g_ctr;

__device__ __forceinline__ float fast_tanh(float x) {
    // tanh(x) = 1 - 2/(1 + exp(2x));  exp(2x) = ex2(x * 2*log2(e))
    float u;
    asm("ex2.approx.f32 %0, %1;" : "=f"(u) : "f"(x * 2.8853900817779268f));
    float r;
    asm("rcp.approx.f32 %0, %1;" : "=f"(r) : "f"(u + 1.0f));
    return fmaf(-2.0f, r, 1.0f);
}

__device__ __forceinline__ float fast_exp2(float x) {
    float y;
    asm("ex2.approx.f32 %0, %1;" : "=f"(y) : "f"(x));
    return y;
}

__global__ void zero_kernel() {
    const int i = blockIdx.x * 256 + threadIdx.x;
    if (i < NB * ND) g_acc[i] = 0.0f;
    if (i < NB)      g_l[i]   = 0.0f;
    if (i == 0)      g_ctr    = 0u;
}

__global__ __launch_bounds__(256, 2)
void memn2n_kernel(const float* __restrict__ story,
                   const float* __restrict__ query,
                   const float* __restrict__ Wa_w)
{
    const int tid  = threadIdx.x;
    const int warp = tid >> 5;
    const int lane = tid & 31;
    const float LOG2E = 1.4426950408889634f;

    __shared__ unsigned s_unit;

    for (;;) {
        if (tid == 0) s_unit = atomicAdd(&g_ctr, 1u);
        __syncthreads();
        const unsigned u = s_unit;
        __syncthreads();                 // protect s_unit before next write
        if (u >= NUNITS) break;          // uniform across CTA

        const int b = (int)(u >> 3);
        const int c = (int)(u & 7);

        // lane owns d = 128*k + 4*lane + j (k=0..3, j=0..3): 4 coalesced float4
        const float* qb = query + b * ND;
        float4 q[4], w[4];
#pragma unroll
        for (int k = 0; k < 4; k++) {
            q[k] = *(const float4*)(qb   + k * 128 + 4 * lane);
            w[k] = *(const float4*)(Wa_w + k * 128 + 4 * lane);
        }

        const float* sb = story + (size_t)b * NS * ND + (size_t)c * CHUNK_S * ND;

        float4 acc[4];
#pragma unroll
        for (int k = 0; k < 4; k++) acc[k] = make_float4(0.f, 0.f, 0.f, 0.f);
        float lsum = 0.0f;

        // software-pipelined streaming of this warp's rows
        float4 x[4], xn[4];
        {
            const float* p = sb + (size_t)warp * ND;
#pragma unroll
            for (int k = 0; k < 4; k++)
                xn[k] = __ldcs((const float4*)(p + k * 128 + 4 * lane));
        }

        for (int s = warp; s < CHUNK_S; s += 8) {
#pragma unroll
            for (int k = 0; k < 4; k++) x[k] = xn[k];

            const int sn = s + 8;
            if (sn < CHUNK_S) {
                const float* p = sb + (size_t)sn * ND;
#pragma unroll
                for (int k = 0; k < 4; k++)
                    xn[k] = __ldcs((const float4*)(p + k * 128 + 4 * lane));
            }

            // score partial: sum_d tanh(x+q)*w  (bias softmax-invariant -> dropped)
            float part = 0.0f;
#pragma unroll
            for (int k = 0; k < 4; k++) {
                part = fmaf(fast_tanh(x[k].x + q[k].x), w[k].x, part);
                part = fmaf(fast_tanh(x[k].y + q[k].y), w[k].y, part);
                part = fmaf(fast_tanh(x[k].z + q[k].z), w[k].z, part);
                part = fmaf(fast_tanh(x[k].w + q[k].w), w[k].w, part);
            }
#pragma unroll
            for (int off = 16; off > 0; off >>= 1)
                part += __shfl_xor_sync(0xffffffffu, part, off);

            // |score| <= ~4 in practice (w ~ N(0,1/512)): no max subtraction needed
            const float p = fast_exp2(part * LOG2E);
            lsum += p;                     // p is warp-uniform: every lane holds full sum
#pragma unroll
            for (int k = 0; k < 4; k++) {
                acc[k].x = fmaf(p, x[k].x, acc[k].x);
                acc[k].y = fmaf(p, x[k].y, acc[k].y);
                acc[k].z = fmaf(p, x[k].z, acc[k].z);
                acc[k].w = fmaf(p, x[k].w, acc[k].w);
            }
        }

        // merge unit partials into L2-resident scratch
        float* ga = g_acc + b * ND;
#pragma unroll
        for (int k = 0; k < 4; k++) {
            const int d0 = k * 128 + 4 * lane;
            atomicAdd(&ga[d0 + 0], acc[k].x);
            atomicAdd(&ga[d0 + 1], acc[k].y);
            atomicAdd(&ga[d0 + 2], acc[k].z);
            atomicAdd(&ga[d0 + 3], acc[k].w);
        }
        // NOTE: no cross-lane reduce here — lsum is already the warp's full sum
        // (p was warp-uniform). R2's shuffle-reduce counted it 32x -> out = ref/32.
        if (lane == 0) atomicAdd(&g_l[b], lsum);
    }
}

__global__ void norm_kernel(float* __restrict__ out) {
    const int i = blockIdx.x * 256 + threadIdx.x;   // grid covers NB*ND
    const int b = i >> 9;                            // ND = 512
    out[i] = g_acc[i] / g_l[b];
}

extern "C" void kernel_launch(void* const* d_in, const int* in_sizes, int n_in,
                              void* d_out, int out_size)
{
    const float* story = (const float*)d_in[0];
    const float* query = (const float*)d_in[1];
    const float* Wa_w  = (const float*)d_in[2];
    // d_in[3] = Wa_b: cancels inside softmax, unused.
    (void)in_sizes; (void)n_in; (void)out_size;

    zero_kernel<<<(NB * ND + 255) / 256, 256>>>();
    memn2n_kernel<<<NCTA, 256>>>(story, query, Wa_w);
    norm_kernel<<<(NB * ND + 255) / 256, 256>>>((float*)d_out);
}

// round 10
// speedup vs baseline: 1.3270x; 1.3270x over previous
#include <cuda_runtime.h>

#define NB 256
#define NS 1024
#define ND 512

__device__ __forceinline__ float hw_tanh(float x) {
    // sm_75+ hardware tanh: single MUFU op, max abs err ~6e-4
    float y;
    asm("tanh.approx.f32 %0, %1;" : "=f"(y) : "f"(x));
    return y;
}

__device__ __forceinline__ float fast_exp2(float x) {
    float y;
    asm("ex2.approx.f32 %0, %1;" : "=f"(y) : "f"(x));
    return y;
}

__global__ __launch_bounds__(256, 2)
void memn2n_kernel(const float* __restrict__ story,
                   const float* __restrict__ query,
                   const float* __restrict__ Wa_w,
                   float* __restrict__ out)
{
    const int b    = blockIdx.x;
    const int tid  = threadIdx.x;
    const int warp = tid >> 5;
    const int lane = tid & 31;

    __shared__ float sm_l[8];
    __shared__ float sm_acc[ND];

    // zero the merge buffer (ordered by the __syncthreads below)
    for (int i = tid; i < ND; i += 256) sm_acc[i] = 0.0f;

    // lane owns d = 128*k + 4*lane + j (k=0..3, j=0..3): 4 coalesced float4
    const float* qb = query + b * ND;
    float4 q[4], w[4];
#pragma unroll
    for (int k = 0; k < 4; k++) {
        q[k] = *(const float4*)(qb   + k * 128 + 4 * lane);
        w[k] = *(const float4*)(Wa_w + k * 128 + 4 * lane);
    }

    const float* sb = story + (size_t)b * NS * ND;

    float lsum = 0.0f;
    float4 acc[4];
#pragma unroll
    for (int k = 0; k < 4; k++) acc[k] = make_float4(0.f, 0.f, 0.f, 0.f);

    const float LOG2E = 1.4426950408889634f;

    // software-pipelined streaming: prefetch first row for this warp
    float4 x[4], xn[4];
    {
        const float* p = sb + (size_t)warp * ND;
#pragma unroll
        for (int k = 0; k < 4; k++)
            xn[k] = __ldcs((const float4*)(p + k * 128 + 4 * lane));
    }

    for (int s = warp; s < NS; s += 8) {
#pragma unroll
        for (int k = 0; k < 4; k++) x[k] = xn[k];

        const int sn = s + 8;
        if (sn < NS) {
            const float* p = sb + (size_t)sn * ND;
#pragma unroll
            for (int k = 0; k < 4; k++)
                xn[k] = __ldcs((const float4*)(p + k * 128 + 4 * lane));
        }

        // score partial: sum_d tanh(x+q)*w  (bias softmax-invariant -> dropped)
        float part = 0.0f;
#pragma unroll
        for (int k = 0; k < 4; k++) {
            part = fmaf(hw_tanh(x[k].x + q[k].x), w[k].x, part);
            part = fmaf(hw_tanh(x[k].y + q[k].y), w[k].y, part);
            part = fmaf(hw_tanh(x[k].z + q[k].z), w[k].z, part);
            part = fmaf(hw_tanh(x[k].w + q[k].w), w[k].w, part);
        }
#pragma unroll
        for (int off = 16; off > 0; off >>= 1)
            part += __shfl_xor_sync(0xffffffffu, part, off);

        // |score| small (w ~ N(0,1/512)): no max subtraction needed
        const float p = fast_exp2(part * LOG2E);
        lsum += p;                       // p is warp-uniform: full sum in every lane
#pragma unroll
        for (int k = 0; k < 4; k++) {
            acc[k].x = fmaf(p, x[k].x, acc[k].x);
            acc[k].y = fmaf(p, x[k].y, acc[k].y);
            acc[k].z = fmaf(p, x[k].z, acc[k].z);
            acc[k].w = fmaf(p, x[k].w, acc[k].w);
        }
    }

    // cross-warp merge (lsum already warp-complete; add once per warp)
    if (lane == 0) sm_l[warp] = lsum;
    __syncthreads();

    float L = 0.0f;
#pragma unroll
    for (int i = 0; i < 8; i++) L += sm_l[i];

#pragma unroll
    for (int k = 0; k < 4; k++) {
        const int d0 = k * 128 + 4 * lane;
        atomicAdd(&sm_acc[d0 + 0], acc[k].x);
        atomicAdd(&sm_acc[d0 + 1], acc[k].y);
        atomicAdd(&sm_acc[d0 + 2], acc[k].z);
        atomicAdd(&sm_acc[d0 + 3], acc[k].w);
    }
    __syncthreads();

    const float inv = 1.0f / L;
    float* ob = out + b * ND;
    for (int i = tid; i < ND; i += 256)
        ob[i] = sm_acc[i] * inv;
}

extern "C" void kernel_launch(void* const* d_in, const int* in_sizes, int n_in,
                              void* d_out, int out_size)
{
    const float* story = (const float*)d_in[0];
    const float* query = (const float*)d_in[1];
    const float* Wa_w  = (const float*)d_in[2];
    // d_in[3] = Wa_b: cancels inside softmax, unused.
    (void)in_sizes; (void)n_in; (void)out_size;

    memn2n_kernel<<<NB, 256>>>(story, query, Wa_w, (float*)d_out);
}